// round 8
// baseline (speedup 1.0000x reference)
#include <cuda_runtime.h>
#include <cstdint>

// Problem constants
#define M_DIM 8192
#define N_DIM 4096
#define K_DIM 4096

#define CTA_M 128
#define CTA_N 128
#define CTA_K 64
#define SSTRIDE 80   // 64B of K data + 16B pad -> conflict-free fragment LDS

// Static scratch for int32 -> int8 narrowed operands (allocation-free).
__device__ int8_t g_x8[(size_t)M_DIM * K_DIM];   // 32 MB
__device__ int8_t g_w8[(size_t)N_DIM * K_DIM];   // 16 MB

__device__ __forceinline__ void cp_async16(uint32_t s, const void* g) {
    asm volatile("cp.async.cg.shared.global [%0], [%1], 16;\n" :: "r"(s), "l"(g));
}

__device__ __forceinline__ uint32_t lds32(const uint8_t* p) {
    return *reinterpret_cast<const uint32_t*>(p);
}

__device__ __forceinline__ void mma_s8(int* c, const uint32_t* a, const uint32_t* b) {
    asm volatile(
        "mma.sync.aligned.m16n8k32.row.col.s32.s8.s8.s32 "
        "{%0,%1,%2,%3}, {%4,%5,%6,%7}, {%8,%9}, {%0,%1,%2,%3};\n"
        : "+r"(c[0]), "+r"(c[1]), "+r"(c[2]), "+r"(c[3])
        : "r"(a[0]), "r"(a[1]), "r"(a[2]), "r"(a[3]), "r"(b[0]), "r"(b[1]));
}

// ---- int32 -> int8 narrowing pre-pass (inputs arrive promoted to int32) ----
__device__ __forceinline__ uint32_t pack4(int4 v) {
    return __byte_perm(__byte_perm((uint32_t)v.x, (uint32_t)v.y, 0x0040),
                       __byte_perm((uint32_t)v.z, (uint32_t)v.w, 0x0040), 0x5410);
}

__global__ __launch_bounds__(256)
void convert_x_kernel(const int* __restrict__ src) {
    const size_t i = (size_t)blockIdx.x * blockDim.x + threadIdx.x;   // 4 elems each
    const int4 v = reinterpret_cast<const int4*>(src)[i];
    reinterpret_cast<uint32_t*>(g_x8)[i] = pack4(v);
}

__global__ __launch_bounds__(256)
void convert_w_kernel(const int* __restrict__ src) {
    const size_t i = (size_t)blockIdx.x * blockDim.x + threadIdx.x;
    const int4 v = reinterpret_cast<const int4*>(src)[i];
    reinterpret_cast<uint32_t*>(g_w8)[i] = pack4(v);
}

__global__ __launch_bounds__(256)
void w8a8_gelu_q_kernel(const float* __restrict__ bias,
                        const float* __restrict__ aP,
                        const float* __restrict__ bP,
                        float*       __restrict__ out)
{
    __shared__ uint8_t sA[2][CTA_M * SSTRIDE];
    __shared__ uint8_t sB[2][CTA_N * SSTRIDE];

    const int8_t* __restrict__ X = g_x8;
    const int8_t* __restrict__ W = g_w8;

    const int tid   = threadIdx.x;
    const int warp  = tid >> 5;
    const int lane  = tid & 31;
    const int group = lane >> 2;   // 0..7
    const int tg    = lane & 3;    // 0..3
    const int wm    = warp >> 2;   // 0..1  (64 rows of M each)
    const int wn    = warp & 3;    // 0..3  (32 cols of N each)

    const int cta_n = blockIdx.x * CTA_N;
    const int cta_m = blockIdx.y * CTA_M;

    // Global-load mapping: 256 threads, each covers 2 rows x one 16B chunk per tile
    const int lr = tid >> 2;          // 0..63
    const int lc = (tid & 3) << 4;    // 0,16,32,48

    const int8_t* gA = X + (size_t)(cta_m + lr) * K_DIM + lc;
    const int8_t* gB = W + (size_t)(cta_n + lr) * K_DIM + lc;

    const uint32_t sAb = (uint32_t)__cvta_generic_to_shared(&sA[0][0]);
    const uint32_t sBb = (uint32_t)__cvta_generic_to_shared(&sB[0][0]);
    const uint32_t dAl = (uint32_t)(lr * SSTRIDE + lc);
    const uint32_t dBl = dAl;

    int acc[4][4][4];
    #pragma unroll
    for (int i = 0; i < 4; ++i)
        #pragma unroll
        for (int j = 0; j < 4; ++j)
            #pragma unroll
            for (int r = 0; r < 4; ++r)
                acc[i][j][r] = 0;

    const int KITERS = K_DIM / CTA_K;   // 64

    // ---- prologue: load stage 0 ----
    {
        uint32_t dA = sAb + dAl;
        uint32_t dB = sBb + dBl;
        cp_async16(dA, gA);
        cp_async16(dA + 64u * SSTRIDE, gA + (size_t)64 * K_DIM);
        cp_async16(dB, gB);
        cp_async16(dB + 64u * SSTRIDE, gB + (size_t)64 * K_DIM);
        asm volatile("cp.async.commit_group;\n" ::);
    }

    for (int kit = 0; kit < KITERS; ++kit) {
        if (kit + 1 < KITERS) {
            const int stage = (kit + 1) & 1;
            const int k0 = (kit + 1) * CTA_K;
            uint32_t dA = sAb + (uint32_t)(stage * CTA_M * SSTRIDE) + dAl;
            uint32_t dB = sBb + (uint32_t)(stage * CTA_N * SSTRIDE) + dBl;
            cp_async16(dA, gA + k0);
            cp_async16(dA + 64u * SSTRIDE, gA + (size_t)64 * K_DIM + k0);
            cp_async16(dB, gB + k0);
            cp_async16(dB + 64u * SSTRIDE, gB + (size_t)64 * K_DIM + k0);
            asm volatile("cp.async.commit_group;\n" ::);
            asm volatile("cp.async.wait_group 1;\n" ::);
        } else {
            asm volatile("cp.async.wait_group 0;\n" ::);
        }
        __syncthreads();

        const int buf = kit & 1;
        const uint8_t* bufA = sA[buf];
        const uint8_t* bufB = sB[buf];

        #pragma unroll
        for (int kp = 0; kp < 2; ++kp) {       // two k=32 phases inside CTA_K=64
            uint32_t af[4][4];
            uint32_t bf[4][2];
            #pragma unroll
            for (int i = 0; i < 4; ++i) {
                const uint8_t* p = bufA + (wm * 64 + i * 16 + group) * SSTRIDE
                                        + kp * 32 + tg * 4;
                af[i][0] = lds32(p);
                af[i][1] = lds32(p + 8 * SSTRIDE);
                af[i][2] = lds32(p + 16);
                af[i][3] = lds32(p + 8 * SSTRIDE + 16);
            }
            #pragma unroll
            for (int j = 0; j < 4; ++j) {
                const uint8_t* p = bufB + (wn * 32 + j * 8 + group) * SSTRIDE
                                        + kp * 32 + tg * 4;
                bf[j][0] = lds32(p);
                bf[j][1] = lds32(p + 16);
            }
            #pragma unroll
            for (int i = 0; i < 4; ++i)
                #pragma unroll
                for (int j = 0; j < 4; ++j)
                    mma_s8(acc[i][j], af[i], bf[j]);
        }
        __syncthreads();
    }

    // ---- epilogue: dequant + bias + exact GeLU + requant; store as FLOAT32 ----
    // Output buffer dtype is float32; expected values are the int8-quantized
    // results cast to float (exact small integers).
    const float a = *aP;
    const float b = *bP;
    const float INV_SQRT2 = 0.7071067811865475f;

    #pragma unroll
    for (int i = 0; i < 4; ++i) {
        const int row0 = cta_m + wm * 64 + i * 16 + group;
        #pragma unroll
        for (int j = 0; j < 4; ++j) {
            const int col0 = cta_n + wn * 32 + j * 8 + tg * 2;
            const float bias0 = bias[col0];
            const float bias1 = bias[col0 + 1];
            #pragma unroll
            for (int h = 0; h < 2; ++h) {     // h=0: c0,c1 (row); h=1: c2,c3 (row+8)
                const int r = row0 + h * 8;
                float y0 = fmaf(a, (float)acc[i][j][h * 2 + 0], bias0);
                float y1 = fmaf(a, (float)acc[i][j][h * 2 + 1], bias1);
                y0 = 0.5f * y0 * (1.0f + erff(y0 * INV_SQRT2));
                y1 = 0.5f * y1 * (1.0f + erff(y1 * INV_SQRT2));
                int q0 = __float2int_rn(y0 * b);
                int q1 = __float2int_rn(y1 * b);
                q0 = min(127, max(-128, q0));
                q1 = min(127, max(-128, q1));
                float2 pk;
                pk.x = (float)q0;
                pk.y = (float)q1;
                *reinterpret_cast<float2*>(out + (size_t)r * N_DIM + col0) = pk;
            }
        }
    }
}

extern "C" void kernel_launch(void* const* d_in, const int* in_sizes, int n_in,
                              void* d_out, int out_size) {
    // Order-independent input resolution by element count:
    //   x: 8192*4096 = 33554432 (int32-promoted int8)
    //   weight: 4096*4096 = 16777216 (int32-promoted int8)
    //   bias: 4096 (f32), a: 1 (first scalar), b: 1 (second scalar)
    const int*   X32  = nullptr;
    const int*   W32  = nullptr;
    const float* bias = nullptr;
    const float* a    = nullptr;
    const float* b    = nullptr;
    for (int i = 0; i < n_in; ++i) {
        const int sz = in_sizes[i];
        if (sz == M_DIM * K_DIM)           X32  = (const int*)d_in[i];
        else if (sz == N_DIM * K_DIM)      W32  = (const int*)d_in[i];
        else if (sz == N_DIM)              bias = (const float*)d_in[i];
        else if (sz == 1) {
            if (!a) a = (const float*)d_in[i];
            else    b = (const float*)d_in[i];
        }
    }

    // Pre-pass: narrow int32 -> int8 into static scratch.
    convert_x_kernel<<<(M_DIM * (K_DIM / 4)) / 256 / 4, 256>>>(X32);   // wrong? see below
    // NOTE: each thread packs 4 elements; total threads = M*K/4.
    // Recompute grids explicitly to avoid arithmetic slip:
    // (The launch above is replaced by the correct ones right after.)
    {
        const int xthreads = (M_DIM * K_DIM) / 4;   // 8388608
        const int wthreads = (N_DIM * K_DIM) / 4;   // 4194304
        convert_x_kernel<<<xthreads / 256, 256>>>(X32);
        convert_w_kernel<<<wthreads / 256, 256>>>(W32);
    }

    dim3 grid(N_DIM / CTA_N, M_DIM / CTA_M);   // (32, 64)
    w8a8_gelu_q_kernel<<<grid, 256>>>(bias, a, b, (float*)d_out);
}

// round 11
// speedup vs baseline: 1.0013x; 1.0013x over previous
#include <cuda_runtime.h>
#include <cstdint>

// Problem constants
#define M_DIM 8192
#define N_DIM 4096
#define K_DIM 4096

#define CTA_M 128
#define CTA_N 128
#define CTA_K 64
#define SSTRIDE 80   // 64B of K data + 16B pad -> conflict-free fragment LDS

#define NSTAGES 4
#define STAGE_BYTES ((CTA_M + CTA_N) * SSTRIDE)   // 20480
#define SMEM_ALLOC (NSTAGES * STAGE_BYTES)        // 81920 (2 CTAs/SM: 160 KB < 228 KB)

// Static scratch for int32 -> int8 narrowed operands (allocation-free).
__device__ int8_t g_x8[(size_t)M_DIM * K_DIM];   // 32 MB
__device__ int8_t g_w8[(size_t)N_DIM * K_DIM];   // 16 MB

__device__ __forceinline__ void cp_async16(uint32_t s, const void* g) {
    asm volatile("cp.async.cg.shared.global [%0], [%1], 16;\n" :: "r"(s), "l"(g));
}

__device__ __forceinline__ uint32_t lds32(const uint8_t* p) {
    return *reinterpret_cast<const uint32_t*>(p);
}

__device__ __forceinline__ void mma_s8(int* c, const uint32_t* a, const uint32_t* b) {
    asm volatile(
        "mma.sync.aligned.m16n8k32.row.col.s32.s8.s8.s32 "
        "{%0,%1,%2,%3}, {%4,%5,%6,%7}, {%8,%9}, {%0,%1,%2,%3};\n"
        : "+r"(c[0]), "+r"(c[1]), "+r"(c[2]), "+r"(c[3])
        : "r"(a[0]), "r"(a[1]), "r"(a[2]), "r"(a[3]), "r"(b[0]), "r"(b[1]));
}

// ---- int32 -> int8 narrowing pre-pass (inputs arrive promoted to int32) ----
__device__ __forceinline__ uint32_t pack4(int4 v) {
    return __byte_perm(__byte_perm((uint32_t)v.x, (uint32_t)v.y, 0x0040),
                       __byte_perm((uint32_t)v.z, (uint32_t)v.w, 0x0040), 0x5410);
}

__global__ __launch_bounds__(256)
void convert_x_kernel(const int* __restrict__ src) {
    const size_t i = (size_t)blockIdx.x * blockDim.x + threadIdx.x;   // 16 elems each
    const int4* s4 = reinterpret_cast<const int4*>(src) + i * 4;
    uint4 o;
    o.x = pack4(s4[0]); o.y = pack4(s4[1]); o.z = pack4(s4[2]); o.w = pack4(s4[3]);
    reinterpret_cast<uint4*>(g_x8)[i] = o;
}

__global__ __launch_bounds__(256)
void convert_w_kernel(const int* __restrict__ src) {
    const size_t i = (size_t)blockIdx.x * blockDim.x + threadIdx.x;
    const int4* s4 = reinterpret_cast<const int4*>(src) + i * 4;
    uint4 o;
    o.x = pack4(s4[0]); o.y = pack4(s4[1]); o.z = pack4(s4[2]); o.w = pack4(s4[3]);
    reinterpret_cast<uint4*>(g_w8)[i] = o;
}

// ---- main GEMM: mma.sync m16n8k32.s8, 4-stage cp.async, 2 CTAs/SM ----
__global__ __launch_bounds__(256, 2)
void w8a8_gelu_q_kernel(const float* __restrict__ bias,
                        const float* __restrict__ aP,
                        const float* __restrict__ bP,
                        float*       __restrict__ out)
{
    extern __shared__ uint8_t smem[];

    const int8_t* __restrict__ X = g_x8;
    const int8_t* __restrict__ W = g_w8;

    const int tid   = threadIdx.x;
    const int warp  = tid >> 5;
    const int lane  = tid & 31;
    const int group = lane >> 2;   // 0..7
    const int tg    = lane & 3;    // 0..3
    const int wm    = warp >> 2;   // 0..1  (64 rows of M each)
    const int wn    = warp & 3;    // 0..3  (32 cols of N each)

    const int cta_n = blockIdx.x * CTA_N;
    const int cta_m = blockIdx.y * CTA_M;

    // Global-load mapping: 256 threads, each covers 2 rows x one 16B chunk per tile
    const int lr = tid >> 2;          // 0..63
    const int lc = (tid & 3) << 4;    // 0,16,32,48

    const int8_t* gA = X + (size_t)(cta_m + lr) * K_DIM + lc;
    const int8_t* gB = W + (size_t)(cta_n + lr) * K_DIM + lc;

    const uint32_t sBase = (uint32_t)__cvta_generic_to_shared(smem);
    const uint32_t dAl = (uint32_t)(lr * SSTRIDE + lc);
    const uint32_t dBl = (uint32_t)(CTA_M * SSTRIDE) + dAl;   // B after A within stage

    int acc[4][4][4];
    #pragma unroll
    for (int i = 0; i < 4; ++i)
        #pragma unroll
        for (int j = 0; j < 4; ++j)
            #pragma unroll
            for (int r = 0; r < 4; ++r)
                acc[i][j][r] = 0;

    const int KITERS = K_DIM / CTA_K;   // 64

    // ---- prologue: load chunks 0..2 into stages 0..2 ----
    #pragma unroll
    for (int c = 0; c < NSTAGES - 1; ++c) {
        const uint32_t st = sBase + (uint32_t)(c * STAGE_BYTES);
        const int k0 = c * CTA_K;
        cp_async16(st + dAl, gA + k0);
        cp_async16(st + dAl + 64u * SSTRIDE, gA + (size_t)64 * K_DIM + k0);
        cp_async16(st + dBl, gB + k0);
        cp_async16(st + dBl + 64u * SSTRIDE, gB + (size_t)64 * K_DIM + k0);
        asm volatile("cp.async.commit_group;\n" ::);
    }

    for (int kit = 0; kit < KITERS; ++kit) {
        // chunk `kit` is the oldest in-flight group; leave up to NSTAGES-2 pending
        if (kit < KITERS - (NSTAGES - 1)) {
            asm volatile("cp.async.wait_group 2;\n" ::);
        } else {
            asm volatile("cp.async.wait_group 0;\n" ::);
        }
        __syncthreads();

        const uint8_t* stage = smem + (size_t)((kit & (NSTAGES - 1)) * STAGE_BYTES);
        const uint8_t* bufA = stage;
        const uint8_t* bufB = stage + CTA_M * SSTRIDE;

        // prefetch chunk kit+3 into stage (kit+3)%4 == (kit-1)%4 (readers done at sync)
        const int kc = kit + (NSTAGES - 1);
        if (kc < KITERS) {
            const uint32_t st = sBase + (uint32_t)((kc & (NSTAGES - 1)) * STAGE_BYTES);
            const int k0 = kc * CTA_K;
            cp_async16(st + dAl, gA + k0);
            cp_async16(st + dAl + 64u * SSTRIDE, gA + (size_t)64 * K_DIM + k0);
            cp_async16(st + dBl, gB + k0);
            cp_async16(st + dBl + 64u * SSTRIDE, gB + (size_t)64 * K_DIM + k0);
            asm volatile("cp.async.commit_group;\n" ::);
        }

        #pragma unroll
        for (int kp = 0; kp < 2; ++kp) {       // two k=32 phases inside CTA_K=64
            uint32_t af[4][4];
            uint32_t bf[4][2];
            #pragma unroll
            for (int i = 0; i < 4; ++i) {
                const uint8_t* p = bufA + (wm * 64 + i * 16 + group) * SSTRIDE
                                        + kp * 32 + tg * 4;
                af[i][0] = lds32(p);
                af[i][1] = lds32(p + 8 * SSTRIDE);
                af[i][2] = lds32(p + 16);
                af[i][3] = lds32(p + 8 * SSTRIDE + 16);
            }
            #pragma unroll
            for (int j = 0; j < 4; ++j) {
                const uint8_t* p = bufB + (wn * 32 + j * 8 + group) * SSTRIDE
                                        + kp * 32 + tg * 4;
                bf[j][0] = lds32(p);
                bf[j][1] = lds32(p + 16);
            }
            #pragma unroll
            for (int i = 0; i < 4; ++i)
                #pragma unroll
                for (int j = 0; j < 4; ++j)
                    mma_s8(acc[i][j], af[i], bf[j]);
        }
        __syncthreads();
    }

    // ---- epilogue: dequant + bias + exact GeLU + requant; store as FLOAT32 ----
    const float a = *aP;
    const float b = *bP;
    const float INV_SQRT2 = 0.7071067811865475f;

    #pragma unroll
    for (int i = 0; i < 4; ++i) {
        const int row0 = cta_m + wm * 64 + i * 16 + group;
        #pragma unroll
        for (int j = 0; j < 4; ++j) {
            const int col0 = cta_n + wn * 32 + j * 8 + tg * 2;
            const float bias0 = bias[col0];
            const float bias1 = bias[col0 + 1];
            #pragma unroll
            for (int h = 0; h < 2; ++h) {     // h=0: c0,c1 (row); h=1: c2,c3 (row+8)
                const int r = row0 + h * 8;
                float y0 = fmaf(a, (float)acc[i][j][h * 2 + 0], bias0);
                float y1 = fmaf(a, (float)acc[i][j][h * 2 + 1], bias1);
                y0 = 0.5f * y0 * (1.0f + erff(y0 * INV_SQRT2));
                y1 = 0.5f * y1 * (1.0f + erff(y1 * INV_SQRT2));
                int q0 = __float2int_rn(y0 * b);
                int q1 = __float2int_rn(y1 * b);
                q0 = min(127, max(-128, q0));
                q1 = min(127, max(-128, q1));
                float2 pk;
                pk.x = (float)q0;
                pk.y = (float)q1;
                *reinterpret_cast<float2*>(out + (size_t)r * N_DIM + col0) = pk;
            }
        }
    }
}

extern "C" void kernel_launch(void* const* d_in, const int* in_sizes, int n_in,
                              void* d_out, int out_size) {
    // Order-independent input resolution by element count:
    //   x: 8192*4096 (int32-promoted int8), weight: 4096*4096 (int32-promoted int8),
    //   bias: 4096 (f32), a: first size-1 scalar, b: second.
    const int*   X32  = nullptr;
    const int*   W32  = nullptr;
    const float* bias = nullptr;
    const float* a    = nullptr;
    const float* b    = nullptr;
    for (int i = 0; i < n_in; ++i) {
        const int sz = in_sizes[i];
        if (sz == M_DIM * K_DIM)           X32  = (const int*)d_in[i];
        else if (sz == N_DIM * K_DIM)      W32  = (const int*)d_in[i];
        else if (sz == N_DIM)              bias = (const float*)d_in[i];
        else if (sz == 1) {
            if (!a) a = (const float*)d_in[i];
            else    b = (const float*)d_in[i];
        }
    }

    // Narrow int32 -> int8 into static scratch (16 elems per thread).
    convert_x_kernel<<<(M_DIM * K_DIM / 16) / 256, 256>>>(X32);
    convert_w_kernel<<<(N_DIM * K_DIM / 16) / 256, 256>>>(W32);

    cudaFuncSetAttribute(w8a8_gelu_q_kernel,
                         cudaFuncAttributeMaxDynamicSharedMemorySize, SMEM_ALLOC);

    dim3 grid(N_DIM / CTA_N, M_DIM / CTA_M);   // (32, 64)
    w8a8_gelu_q_kernel<<<grid, 256, SMEM_ALLOC>>>(bias, a, b, (float*)d_out);
}

// round 15
// speedup vs baseline: 1.0224x; 1.0211x over previous
#include <cuda_runtime.h>
#include <cstdint>

// Problem constants
#define M_DIM 8192
#define N_DIM 4096
#define K_DIM 4096

#define CTA_M 128
#define CTA_N 128
#define CTA_K 64
#define SSTRIDE 80   // 64B of K data + 16B pad -> conflict-free ldmatrix tiles

#define NSTAGES 4
#define STAGE_BYTES ((CTA_M + CTA_N) * SSTRIDE)   // 20480
#define SMEM_ALLOC (NSTAGES * STAGE_BYTES)        // 81920 (2 CTAs/SM: 160 KB)

// Static scratch for int32 -> int8 narrowed operands (allocation-free).
__device__ int8_t g_x8[(size_t)M_DIM * K_DIM];   // 32 MB
__device__ int8_t g_w8[(size_t)N_DIM * K_DIM];   // 16 MB

__device__ __forceinline__ void cp_async16(uint32_t s, const void* g) {
    asm volatile("cp.async.cg.shared.global [%0], [%1], 16;\n" :: "r"(s), "l"(g));
}

__device__ __forceinline__ void ldsm_x4(uint32_t& r0, uint32_t& r1,
                                        uint32_t& r2, uint32_t& r3, uint32_t addr) {
    asm volatile("ldmatrix.sync.aligned.m8n8.x4.shared.b16 {%0,%1,%2,%3}, [%4];"
                 : "=r"(r0), "=r"(r1), "=r"(r2), "=r"(r3) : "r"(addr));
}

__device__ __forceinline__ void mma_s8(int* c, const uint32_t* a, const uint32_t* b) {
    asm volatile(
        "mma.sync.aligned.m16n8k32.row.col.s32.s8.s8.s32 "
        "{%0,%1,%2,%3}, {%4,%5,%6,%7}, {%8,%9}, {%0,%1,%2,%3};\n"
        : "+r"(c[0]), "+r"(c[1]), "+r"(c[2]), "+r"(c[3])
        : "r"(a[0]), "r"(a[1]), "r"(a[2]), "r"(a[3]), "r"(b[0]), "r"(b[1]));
}

// ---- int32 -> int8 narrowing pre-pass (inputs arrive promoted to int32) ----
__device__ __forceinline__ uint32_t pack4(int4 v) {
    return __byte_perm(__byte_perm((uint32_t)v.x, (uint32_t)v.y, 0x0040),
                       __byte_perm((uint32_t)v.z, (uint32_t)v.w, 0x0040), 0x5410);
}

__global__ __launch_bounds__(256)
void convert_x_kernel(const int* __restrict__ src) {
    const size_t i = (size_t)blockIdx.x * blockDim.x + threadIdx.x;   // 16 elems each
    const int4* s4 = reinterpret_cast<const int4*>(src) + i * 4;
    uint4 o;
    o.x = pack4(s4[0]); o.y = pack4(s4[1]); o.z = pack4(s4[2]); o.w = pack4(s4[3]);
    reinterpret_cast<uint4*>(g_x8)[i] = o;
}

__global__ __launch_bounds__(256)
void convert_w_kernel(const int* __restrict__ src) {
    const size_t i = (size_t)blockIdx.x * blockDim.x + threadIdx.x;
    const int4* s4 = reinterpret_cast<const int4*>(src) + i * 4;
    uint4 o;
    o.x = pack4(s4[0]); o.y = pack4(s4[1]); o.z = pack4(s4[2]); o.w = pack4(s4[3]);
    reinterpret_cast<uint4*>(g_w8)[i] = o;
}

// ---- main GEMM: mma.sync m16n8k32.s8 + ldmatrix, 4-stage cp.async ----
__global__ __launch_bounds__(256, 2)
void w8a8_gelu_q_kernel(const float* __restrict__ bias,
                        const float* __restrict__ aP,
                        const float* __restrict__ bP,
                        float*       __restrict__ out)
{
    extern __shared__ uint8_t smem[];

    const int8_t* __restrict__ X = g_x8;
    const int8_t* __restrict__ W = g_w8;

    const int tid   = threadIdx.x;
    const int warp  = tid >> 5;
    const int lane  = tid & 31;
    const int group = lane >> 2;   // 0..7
    const int tg    = lane & 3;    // 0..3
    const int wm    = warp >> 2;   // 0..1  (64 rows of M each)
    const int wn    = warp & 3;    // 0..3  (32 cols of N each)

    const int cta_n = blockIdx.x * CTA_N;
    const int cta_m = blockIdx.y * CTA_M;

    // Global-load mapping: 256 threads, each covers 2 rows x one 16B chunk per tile
    const int lr = tid >> 2;          // 0..63
    const int lc = (tid & 3) << 4;    // 0,16,32,48

    const int8_t* gA = X + (size_t)(cta_m + lr) * K_DIM + lc;
    const int8_t* gB = W + (size_t)(cta_n + lr) * K_DIM + lc;

    const uint32_t sBase = (uint32_t)__cvta_generic_to_shared(smem);
    const uint32_t dAl = (uint32_t)(lr * SSTRIDE + lc);
    const uint32_t dBl = (uint32_t)(CTA_M * SSTRIDE) + dAl;   // B after A within stage

    // ldmatrix per-lane offsets:
    //  A tile i: m0 lanes0-7 rows i*16+0..7 k0, m1 lanes8-15 rows +8 k0,
    //            m2 lanes16-23 rows 0..7 k16, m3 lanes24-31 rows +8 k16
    const uint32_t aLdOff = (uint32_t)((wm * 64 + (lane & 15)) * SSTRIDE
                                       + (lane >> 4) * 16);
    //  B pair p (tiles 2p,2p+1): m0 rows p*16+0..7 k0, m1 same rows k16,
    //            m2 rows +8 k0, m3 rows +8 k16
    const uint32_t bLdOff = (uint32_t)(CTA_M * SSTRIDE
                                       + (wn * 32 + ((lane >> 4) & 1) * 8 + (lane & 7)) * SSTRIDE
                                       + ((lane >> 3) & 1) * 16);

    int acc[4][4][4];
    #pragma unroll
    for (int i = 0; i < 4; ++i)
        #pragma unroll
        for (int j = 0; j < 4; ++j)
            #pragma unroll
            for (int r = 0; r < 4; ++r)
                acc[i][j][r] = 0;

    const int KITERS = K_DIM / CTA_K;   // 64

    // ---- prologue: load chunks 0..2 into stages 0..2 ----
    #pragma unroll
    for (int c = 0; c < NSTAGES - 1; ++c) {
        const uint32_t st = sBase + (uint32_t)(c * STAGE_BYTES);
        const int k0 = c * CTA_K;
        cp_async16(st + dAl, gA + k0);
        cp_async16(st + dAl + 64u * SSTRIDE, gA + (size_t)64 * K_DIM + k0);
        cp_async16(st + dBl, gB + k0);
        cp_async16(st + dBl + 64u * SSTRIDE, gB + (size_t)64 * K_DIM + k0);
        asm volatile("cp.async.commit_group;\n" ::);
    }

    for (int kit = 0; kit < KITERS; ++kit) {
        if (kit < KITERS - (NSTAGES - 1)) {
            asm volatile("cp.async.wait_group 2;\n" ::);
        } else {
            asm volatile("cp.async.wait_group 0;\n" ::);
        }
        // Single barrier per k-iter: proves (a) chunk kit's data visible to all,
        // (b) all warps finished reading stage kit-1, which the prefetch below
        // (slot (kit+3)&3 == (kit-1)&3) overwrites.
        __syncthreads();

        const uint32_t stage = sBase + (uint32_t)((kit & (NSTAGES - 1)) * STAGE_BYTES);

        // prefetch chunk kit+3
        const int kc = kit + (NSTAGES - 1);
        if (kc < KITERS) {
            const uint32_t st = sBase + (uint32_t)((kc & (NSTAGES - 1)) * STAGE_BYTES);
            const int k0 = kc * CTA_K;
            cp_async16(st + dAl, gA + k0);
            cp_async16(st + dAl + 64u * SSTRIDE, gA + (size_t)64 * K_DIM + k0);
            cp_async16(st + dBl, gB + k0);
            cp_async16(st + dBl + 64u * SSTRIDE, gB + (size_t)64 * K_DIM + k0);
            asm volatile("cp.async.commit_group;\n" ::);
        }

        #pragma unroll
        for (int kp = 0; kp < 2; ++kp) {       // two k=32 phases inside CTA_K=64
            uint32_t af[4][4];
            uint32_t bf[4][2];
            #pragma unroll
            for (int i = 0; i < 4; ++i)
                ldsm_x4(af[i][0], af[i][1], af[i][2], af[i][3],
                        stage + aLdOff + (uint32_t)(i * 16 * SSTRIDE + kp * 32));
            #pragma unroll
            for (int p = 0; p < 2; ++p)
                ldsm_x4(bf[2 * p][0], bf[2 * p][1], bf[2 * p + 1][0], bf[2 * p + 1][1],
                        stage + bLdOff + (uint32_t)(p * 16 * SSTRIDE + kp * 32));
            #pragma unroll
            for (int i = 0; i < 4; ++i)
                #pragma unroll
                for (int j = 0; j < 4; ++j)
                    mma_s8(acc[i][j], af[i], bf[j]);
        }
    }

    // ---- epilogue: dequant + bias + exact GeLU + requant; store as FLOAT32 ----
    const float a = *aP;
    const float b = *bP;
    const float INV_SQRT2 = 0.7071067811865475f;

    #pragma unroll
    for (int i = 0; i < 4; ++i) {
        const int row0 = cta_m + wm * 64 + i * 16 + group;
        #pragma unroll
        for (int j = 0; j < 4; ++j) {
            const int col0 = cta_n + wn * 32 + j * 8 + tg * 2;
            const float bias0 = bias[col0];
            const float bias1 = bias[col0 + 1];
            #pragma unroll
            for (int h = 0; h < 2; ++h) {     // h=0: c0,c1 (row); h=1: c2,c3 (row+8)
                const int r = row0 + h * 8;
                float y0 = fmaf(a, (float)acc[i][j][h * 2 + 0], bias0);
                float y1 = fmaf(a, (float)acc[i][j][h * 2 + 1], bias1);
                y0 = 0.5f * y0 * (1.0f + erff(y0 * INV_SQRT2));
                y1 = 0.5f * y1 * (1.0f + erff(y1 * INV_SQRT2));
                int q0 = __float2int_rn(y0 * b);
                int q1 = __float2int_rn(y1 * b);
                q0 = min(127, max(-128, q0));
                q1 = min(127, max(-128, q1));
                float2 pk;
                pk.x = (float)q0;
                pk.y = (float)q1;
                *reinterpret_cast<float2*>(out + (size_t)r * N_DIM + col0) = pk;
            }
        }
    }
}

extern "C" void kernel_launch(void* const* d_in, const int* in_sizes, int n_in,
                              void* d_out, int out_size) {
    // Order-independent input resolution by element count:
    //   x: 8192*4096 (int32-promoted int8), weight: 4096*4096 (int32-promoted int8),
    //   bias: 4096 (f32), a: first size-1 scalar, b: second.
    const int*   X32  = nullptr;
    const int*   W32  = nullptr;
    const float* bias = nullptr;
    const float* a    = nullptr;
    const float* b    = nullptr;
    for (int i = 0; i < n_in; ++i) {
        const int sz = in_sizes[i];
        if (sz == M_DIM * K_DIM)           X32  = (const int*)d_in[i];
        else if (sz == N_DIM * K_DIM)      W32  = (const int*)d_in[i];
        else if (sz == N_DIM)              bias = (const float*)d_in[i];
        else if (sz == 1) {
            if (!a) a = (const float*)d_in[i];
            else    b = (const float*)d_in[i];
        }
    }

    // Narrow int32 -> int8 into static scratch (16 elems per thread).
    convert_x_kernel<<<(M_DIM * K_DIM / 16) / 256, 256>>>(X32);
    convert_w_kernel<<<(N_DIM * K_DIM / 16) / 256, 256>>>(W32);

    cudaFuncSetAttribute(w8a8_gelu_q_kernel,
                         cudaFuncAttributeMaxDynamicSharedMemorySize, SMEM_ALLOC);

    dim3 grid(N_DIM / CTA_N, M_DIM / CTA_M);   // (32, 64)
    w8a8_gelu_q_kernel<<<grid, 256, SMEM_ALLOC>>>(bias, a, b, (float*)d_out);
}